// round 1
// baseline (speedup 1.0000x reference)
#include <cuda_runtime.h>
#include <cstdint>

#define NC     16      // clusters
#define CS     32      // cluster size
#define NH     16      // hidden
#define NF     512     // features = NC*CS
#define BATCH  131072
#define RROWS  16      // rows per block tile
#define THREADS 512

// Fused per-cluster weights: W[n][c][k] = sum_h dec_w[n][c][h]*enc_w[n][h][k]
__device__ float g_W[NC * CS * CS];
__device__ float g_bias[NC * CS];
__device__ int   g_pos[NF];   // pos[feature] = n*32+k  (inverse of clusters perm)

__global__ void prep_kernel(const float* __restrict__ enc_w,
                            const float* __restrict__ enc_b,
                            const float* __restrict__ dec_w,
                            const float* __restrict__ dec_b,
                            const int*   __restrict__ clusters) {
    int t = blockIdx.x * blockDim.x + threadIdx.x;
    if (t < NC * CS * CS) {
        int n = t >> 10;
        int c = (t >> 5) & 31;
        int k = t & 31;
        const float* dw = dec_w + (n * CS + c) * NH;
        const float* ew = enc_w + n * NH * CS + k;
        float s = 0.f;
#pragma unroll
        for (int h = 0; h < NH; h++) s += dw[h] * ew[h * CS];
        g_W[t] = s;
    }
    if (t < NC * CS) {
        int n = t >> 5;
        const float* dw = dec_w + t * NH;
        const float* eb = enc_b + n * NH;
        float s = dec_b[t];
#pragma unroll
        for (int h = 0; h < NH; h++) s += dw[h] * eb[h];
        g_bias[t] = s;
        g_pos[clusters[t]] = t;
    }
}

__global__ void __launch_bounds__(THREADS, 2)
ensemble_kernel(const float* __restrict__ x, float* __restrict__ y) {
    __shared__ __align__(16) float tile[RROWS * NF];

    const int tid  = threadIdx.x;
    const int warp = tid >> 5;       // cluster index
    const int lane = tid & 31;       // output index within cluster
    const long long row0 = (long long)blockIdx.x * RROWS;

    // ---- prologue: this lane's fused weight row as 16 packed f32 pairs ----
    unsigned long long w[CS / 2];
    {
        const unsigned long long* wp =
            (const unsigned long long*)(g_W + ((warp << 5) + lane) * CS);
#pragma unroll
        for (int j = 0; j < CS / 2; j++) w[j] = wp[j];
    }
    const float bias = g_bias[(warp << 5) + lane];

    // ---- load phase: coalesced global read, permuted scatter into smem ----
    {
        const float4* xv = (const float4*)(x) + row0 * (NF / 4);
        const int4*   pv = (const int4*)g_pos;
#pragma unroll
        for (int i = 0; i < (RROWS * NF / 4) / THREADS; i++) {
            int q  = tid + i * THREADS;   // float4 index within tile
            int r  = q >> 7;              // 128 float4 per row
            int f4 = q & 127;
            float4 v = xv[q];
            int4   p = pv[f4];
            float* dst = tile + r * NF;
            dst[p.x] = v.x;
            dst[p.y] = v.y;
            dst[p.z] = v.z;
            dst[p.w] = v.w;
        }
    }
    __syncthreads();

    // ---- compute phase: per row, 8 broadcast LDS.v2.u64 + 16 fma.f32x2 ----
    uint32_t sbase;
    {
        const float* base = tile + (warp << 5);
        asm("{ .reg .u64 t0; cvta.to.shared.u64 t0, %1; cvt.u32.u64 %0, t0; }"
            : "=r"(sbase) : "l"(base));
    }

    float* yout = y + row0 * NF + (warp << 5) + lane;

#pragma unroll
    for (int r = 0; r < RROWS; r++) {
        uint32_t a = sbase + (uint32_t)(r * NF * 4);
        unsigned long long acc0, acc1;
#pragma unroll
        for (int j = 0; j < 4; j++) {
            unsigned long long q0, q1, q2, q3;
            asm volatile("ld.shared.v2.u64 {%0,%1},[%2];"
                         : "=l"(q0), "=l"(q1) : "r"(a + j * 32));
            asm volatile("ld.shared.v2.u64 {%0,%1},[%2];"
                         : "=l"(q2), "=l"(q3) : "r"(a + j * 32 + 16));
            if (j == 0) {
                asm("mul.rn.f32x2 %0,%1,%2;"    : "=l"(acc0) : "l"(w[0]), "l"(q0));
                asm("mul.rn.f32x2 %0,%1,%2;"    : "=l"(acc1) : "l"(w[1]), "l"(q1));
            } else {
                asm("fma.rn.f32x2 %0,%1,%2,%0;" : "+l"(acc0) : "l"(w[4 * j]),     "l"(q0));
                asm("fma.rn.f32x2 %0,%1,%2,%0;" : "+l"(acc1) : "l"(w[4 * j + 1]), "l"(q1));
            }
            asm("fma.rn.f32x2 %0,%1,%2,%0;" : "+l"(acc0) : "l"(w[4 * j + 2]), "l"(q2));
            asm("fma.rn.f32x2 %0,%1,%2,%0;" : "+l"(acc1) : "l"(w[4 * j + 3]), "l"(q3));
        }
        asm("add.rn.f32x2 %0,%0,%1;" : "+l"(acc0) : "l"(acc1));
        uint32_t lo, hi;
        asm("mov.b64 {%0,%1},%2;" : "=r"(lo), "=r"(hi) : "l"(acc0));
        yout[r * NF] = __uint_as_float(lo) + __uint_as_float(hi) + bias;
    }
}

extern "C" void kernel_launch(void* const* d_in, const int* in_sizes, int n_in,
                              void* d_out, int out_size) {
    const float* x        = (const float*)d_in[0];
    const int*   clusters = (const int*)  d_in[1];
    const float* enc_w    = (const float*)d_in[2];
    const float* enc_b    = (const float*)d_in[3];
    const float* dec_w    = (const float*)d_in[4];
    const float* dec_b    = (const float*)d_in[5];
    float*       y        = (float*)d_out;

    prep_kernel<<<32, 512>>>(enc_w, enc_b, dec_w, dec_b, clusters);
    ensemble_kernel<<<BATCH / RROWS, THREADS>>>(x, y);
}

// round 4
// speedup vs baseline: 1.0050x; 1.0050x over previous
#include <cuda_runtime.h>
#include <cstdint>

#define NC     16      // clusters
#define CS     32      // cluster size
#define NH     16      // hidden
#define NF     512     // features = NC*CS
#define BATCH  131072
#define RROWS  16      // rows per block tile
#define THREADS 512

// Fused per-cluster weights: W[n][c][k] = sum_h dec_w[n][c][h]*enc_w[n][h][k]
__device__ float g_W[NC * CS * CS];
__device__ float g_bias[NC * CS];
__device__ int   g_pos[NF];   // pos[feature] = n*32+k  (inverse of clusters perm)

__global__ void prep_kernel(const float* __restrict__ enc_w,
                            const float* __restrict__ enc_b,
                            const float* __restrict__ dec_w,
                            const float* __restrict__ dec_b,
                            const int*   __restrict__ clusters) {
    int t = blockIdx.x * blockDim.x + threadIdx.x;
    if (t < NC * CS * CS) {
        int n = t >> 10;
        int c = (t >> 5) & 31;
        int k = t & 31;
        const float* dw = dec_w + (n * CS + c) * NH;
        const float* ew = enc_w + n * NH * CS + k;
        float s = 0.f;
#pragma unroll
        for (int h = 0; h < NH; h++) s += dw[h] * ew[h * CS];
        g_W[t] = s;
    }
    if (t < NC * CS) {
        int n = t >> 5;
        const float* dw = dec_w + t * NH;
        const float* eb = enc_b + n * NH;
        float s = dec_b[t];
#pragma unroll
        for (int h = 0; h < NH; h++) s += dw[h] * eb[h];
        g_bias[t] = s;
        g_pos[clusters[t]] = t;
    }
}

__global__ void __launch_bounds__(THREADS, 2)
ensemble_kernel(const float* __restrict__ x, float* __restrict__ y) {
    __shared__ __align__(16) float tile[RROWS * NF];

    const int tid  = threadIdx.x;
    const int warp = tid >> 5;       // cluster index
    const int lane = tid & 31;       // output index within cluster
    const long long row0 = (long long)blockIdx.x * RROWS;

    // ---- prologue: this lane's fused weight row as 16 packed f32 pairs ----
    unsigned long long w[CS / 2];
    {
        const unsigned long long* wp =
            (const unsigned long long*)(g_W + ((warp << 5) + lane) * CS);
#pragma unroll
        for (int j = 0; j < CS / 2; j++) w[j] = wp[j];
    }
    const float bias = g_bias[(warp << 5) + lane];

    // ---- load phase: coalesced global read, permuted scatter into smem ----
    {
        const float4* xv = (const float4*)(x) + row0 * (NF / 4);
        const int4*   pv = (const int4*)g_pos;
#pragma unroll
        for (int i = 0; i < (RROWS * NF / 4) / THREADS; i++) {
            int q  = tid + i * THREADS;   // float4 index within tile
            int r  = q >> 7;              // 128 float4 per row
            int f4 = q & 127;
            float4 v = xv[q];
            int4   p = pv[f4];
            float* dst = tile + r * NF;
            dst[p.x] = v.x;
            dst[p.y] = v.y;
            dst[p.z] = v.z;
            dst[p.w] = v.w;
        }
    }
    __syncthreads();

    // ---- compute phase: per row, 8 broadcast LDS.v2.u64 + 16 fma.f32x2 ----
    uint32_t sbase;
    {
        const float* base = tile + (warp << 5);
        asm("{ .reg .u64 t0; cvta.to.shared.u64 t0, %1; cvt.u32.u64 %0, t0; }"
            : "=r"(sbase) : "l"(base));
    }

    float* yout = y + row0 * NF + (warp << 5) + lane;

#pragma unroll
    for (int r = 0; r < RROWS; r++) {
        uint32_t a = sbase + (uint32_t)(r * NF * 4);
        unsigned long long acc0, acc1;
#pragma unroll
        for (int j = 0; j < 4; j++) {
            unsigned long long q0, q1, q2, q3;
            asm volatile("ld.shared.v2.u64 {%0,%1},[%2];"
                         : "=l"(q0), "=l"(q1) : "r"(a + j * 32));
            asm volatile("ld.shared.v2.u64 {%0,%1},[%2];"
                         : "=l"(q2), "=l"(q3) : "r"(a + j * 32 + 16));
            if (j == 0) {
                asm("mul.rn.f32x2 %0,%1,%2;"    : "=l"(acc0) : "l"(w[0]), "l"(q0));
                asm("mul.rn.f32x2 %0,%1,%2;"    : "=l"(acc1) : "l"(w[1]), "l"(q1));
            } else {
                asm("fma.rn.f32x2 %0,%1,%2,%0;" : "+l"(acc0) : "l"(w[4 * j]),     "l"(q0));
                asm("fma.rn.f32x2 %0,%1,%2,%0;" : "+l"(acc1) : "l"(w[4 * j + 1]), "l"(q1));
            }
            asm("fma.rn.f32x2 %0,%1,%2,%0;" : "+l"(acc0) : "l"(w[4 * j + 2]), "l"(q2));
            asm("fma.rn.f32x2 %0,%1,%2,%0;" : "+l"(acc1) : "l"(w[4 * j + 3]), "l"(q3));
        }
        asm("add.rn.f32x2 %0,%0,%1;" : "+l"(acc0) : "l"(acc1));
        uint32_t lo, hi;
        asm("mov.b64 {%0,%1},%2;" : "=r"(lo), "=r"(hi) : "l"(acc0));
        yout[r * NF] = __uint_as_float(lo) + __uint_as_float(hi) + bias;
    }
}

extern "C" void kernel_launch(void* const* d_in, const int* in_sizes, int n_in,
                              void* d_out, int out_size) {
    const float* x        = (const float*)d_in[0];
    const int*   clusters = (const int*)  d_in[1];
    const float* enc_w    = (const float*)d_in[2];
    const float* enc_b    = (const float*)d_in[3];
    const float* dec_w    = (const float*)d_in[4];
    const float* dec_b    = (const float*)d_in[5];
    float*       y        = (float*)d_out;

    prep_kernel<<<32, 512>>>(enc_w, enc_b, dec_w, dec_b, clusters);
    ensemble_kernel<<<BATCH / RROWS, THREADS>>>(x, y);
}

// round 7
// speedup vs baseline: 1.6810x; 1.6727x over previous
#include <cuda_runtime.h>
#include <cstdint>

#define NC     16      // clusters
#define CS     32      // cluster size
#define NH     16      // hidden
#define NF     512     // features = NC*CS
#define BATCH  131072
#define RROWS  64      // rows per block tile
#define THREADS 256
#define TSTRIDE 516    // padded row stride (floats): 516 mod 32 = 4 -> conflict-free scheme

// Fused per-cluster weights: W[n][c][k] = sum_h dec_w[n][c][h]*enc_w[n][h][k]
__device__ float g_W[NC * CS * CS];
__device__ float g_bias[NC * CS];
__device__ int   g_pos[NF];   // pos[feature] = n*32+k  (inverse of clusters perm)

__global__ void prep_kernel(const float* __restrict__ enc_w,
                            const float* __restrict__ enc_b,
                            const float* __restrict__ dec_w,
                            const float* __restrict__ dec_b,
                            const int*   __restrict__ clusters) {
    int t = blockIdx.x * blockDim.x + threadIdx.x;
    if (t < NC * CS * CS) {
        int n = t >> 10;
        int c = (t >> 5) & 31;
        int k = t & 31;
        const float* dw = dec_w + (n * CS + c) * NH;
        const float* ew = enc_w + n * NH * CS + k;
        float s = 0.f;
#pragma unroll
        for (int h = 0; h < NH; h++) s += dw[h] * ew[h * CS];
        g_W[t] = s;
    }
    if (t < NC * CS) {
        int n = t >> 5;
        const float* dw = dec_w + t * NH;
        const float* eb = enc_b + n * NH;
        float s = dec_b[t];
#pragma unroll
        for (int h = 0; h < NH; h++) s += dw[h] * eb[h];
        g_bias[t] = s;
        g_pos[clusters[t]] = t;
    }
}

// P=4 scheme: warp = cluster (2 clusters sequentially). Lane = rg*8+q:
//   rg in 0..3 = row within 4-row group, q in 0..7 = output quad (outputs 4q..4q+3).
// Each lane reads its row's 128B cluster segment as 8 rotated 16B chunks:
// all 32 lane addresses distinct & bank-conflict-free (stride 516).
__global__ void __launch_bounds__(THREADS, 1)
ensemble_kernel(const float* __restrict__ x, float* __restrict__ y) {
    extern __shared__ __align__(16) float tile[];   // RROWS * TSTRIDE floats

    const int tid  = threadIdx.x;
    const int warp = tid >> 5;       // 0..7
    const int lane = tid & 31;
    const int rg   = lane >> 3;      // 0..3
    const int q    = lane & 7;       // 0..7
    const long long row0 = (long long)blockIdx.x * RROWS;

    // ---- load phase: coalesced global read, permuted scatter into smem ----
    {
        const float4* xv = (const float4*)(x) + row0 * (NF / 4);
        const int4*   pv = (const int4*)g_pos;
#pragma unroll 4
        for (int i = 0; i < (RROWS * NF / 4) / THREADS; i++) {
            int idx = tid + i * THREADS;  // float4 index within tile
            int r   = idx >> 7;           // 128 float4 per row
            int f4  = idx & 127;
            float4 v = xv[idx];
            int4   p = pv[f4];
            float* dst = tile + r * TSTRIDE;
            dst[p.x] = v.x;
            dst[p.y] = v.y;
            dst[p.z] = v.z;
            dst[p.w] = v.w;
        }
    }
    __syncthreads();

    uint32_t sb;
    asm("{ .reg .u64 t0; cvta.to.shared.u64 t0, %1; cvt.u32.u64 %0, t0; }"
        : "=r"(sb) : "l"(tile));

    // ---- compute: 2 clusters per warp, W register-stationary per cluster ----
#pragma unroll 1
    for (int half = 0; half < 2; half++) {
        const int cl = warp + half * 8;

        // Load this lane's 4 weight rows (rotated by q so chunk index is static).
        // w[o][2j], w[o][2j+1] = W[cl][4q+o][ch*4 .. ch*4+3] where ch = (q+j)&7.
        unsigned long long w[4][16];
#pragma unroll
        for (int o = 0; o < 4; o++) {
            const float* wr = g_W + (cl * CS + 4 * q + o) * CS;
#pragma unroll
            for (int j = 0; j < 8; j++) {
                int ch = (q + j) & 7;
                ulonglong2 v = *(const ulonglong2*)(wr + ch * 4);
                w[o][2 * j]     = v.x;
                w[o][2 * j + 1] = v.y;
            }
        }
        const float4 bias = *(const float4*)(g_bias + cl * CS + 4 * q);

        float* ybase = y + row0 * NF + cl * CS + q * 4;

#pragma unroll 1
        for (int it = 0; it < RROWS / 4; it++) {
            const int row = it * 4 + rg;
            const uint32_t base = sb + (uint32_t)((row * TSTRIDE + cl * CS) * 4);

            unsigned long long a0 = 0, a1 = 0, a2 = 0, a3 = 0;
#pragma unroll
            for (int j = 0; j < 8; j++) {
                unsigned long long x0, x1;
                uint32_t addr = base + (uint32_t)(((q + j) & 7) << 4);
                asm volatile("ld.shared.v2.u64 {%0,%1},[%2];"
                             : "=l"(x0), "=l"(x1) : "r"(addr));
                if (j == 0) {
                    asm("mul.rn.f32x2 %0,%1,%2;" : "=l"(a0) : "l"(w[0][0]), "l"(x0));
                    asm("mul.rn.f32x2 %0,%1,%2;" : "=l"(a1) : "l"(w[1][0]), "l"(x0));
                    asm("mul.rn.f32x2 %0,%1,%2;" : "=l"(a2) : "l"(w[2][0]), "l"(x0));
                    asm("mul.rn.f32x2 %0,%1,%2;" : "=l"(a3) : "l"(w[3][0]), "l"(x0));
                } else {
                    asm("fma.rn.f32x2 %0,%1,%2,%0;" : "+l"(a0) : "l"(w[0][2 * j]), "l"(x0));
                    asm("fma.rn.f32x2 %0,%1,%2,%0;" : "+l"(a1) : "l"(w[1][2 * j]), "l"(x0));
                    asm("fma.rn.f32x2 %0,%1,%2,%0;" : "+l"(a2) : "l"(w[2][2 * j]), "l"(x0));
                    asm("fma.rn.f32x2 %0,%1,%2,%0;" : "+l"(a3) : "l"(w[3][2 * j]), "l"(x0));
                }
                asm("fma.rn.f32x2 %0,%1,%2,%0;" : "+l"(a0) : "l"(w[0][2 * j + 1]), "l"(x1));
                asm("fma.rn.f32x2 %0,%1,%2,%0;" : "+l"(a1) : "l"(w[1][2 * j + 1]), "l"(x1));
                asm("fma.rn.f32x2 %0,%1,%2,%0;" : "+l"(a2) : "l"(w[2][2 * j + 1]), "l"(x1));
                asm("fma.rn.f32x2 %0,%1,%2,%0;" : "+l"(a3) : "l"(w[3][2 * j + 1]), "l"(x1));
            }

            uint32_t lo, hi;
            float4 out;
            asm("mov.b64 {%0,%1},%2;" : "=r"(lo), "=r"(hi) : "l"(a0));
            out.x = __uint_as_float(lo) + __uint_as_float(hi) + bias.x;
            asm("mov.b64 {%0,%1},%2;" : "=r"(lo), "=r"(hi) : "l"(a1));
            out.y = __uint_as_float(lo) + __uint_as_float(hi) + bias.y;
            asm("mov.b64 {%0,%1},%2;" : "=r"(lo), "=r"(hi) : "l"(a2));
            out.z = __uint_as_float(lo) + __uint_as_float(hi) + bias.z;
            asm("mov.b64 {%0,%1},%2;" : "=r"(lo), "=r"(hi) : "l"(a3));
            out.w = __uint_as_float(lo) + __uint_as_float(hi) + bias.w;

            *(float4*)(ybase + (size_t)row * NF) = out;
        }
        // no __syncthreads needed between halves: tile is read-only here
    }
}

extern "C" void kernel_launch(void* const* d_in, const int* in_sizes, int n_in,
                              void* d_out, int out_size) {
    const float* x        = (const float*)d_in[0];
    const int*   clusters = (const int*)  d_in[1];
    const float* enc_w    = (const float*)d_in[2];
    const float* enc_b    = (const float*)d_in[3];
    const float* dec_w    = (const float*)d_in[4];
    const float* dec_b    = (const float*)d_in[5];
    float*       y        = (float*)d_out;

    static int smem_set = 0;
    const int smem_bytes = RROWS * TSTRIDE * sizeof(float);  // 132096
    if (!smem_set) {
        cudaFuncSetAttribute(ensemble_kernel,
                             cudaFuncAttributeMaxDynamicSharedMemorySize, smem_bytes);
        smem_set = 1;
    }

    prep_kernel<<<32, 512>>>(enc_w, enc_b, dec_w, dec_b, clusters);
    ensemble_kernel<<<BATCH / RROWS, THREADS, smem_bytes>>>(x, y);
}